// round 4
// baseline (speedup 1.0000x reference)
#include <cuda_runtime.h>
#include <stdint.h>

// ---------------------------------------------------------------------------
// LogSqrt2Quantizer — single fused kernel.
//
// Math collapse: the whole chain
//   x_int = rint(x / s_x); y = rint(-log2(x_int + bias)) * c;
//   q = clip(rint(y/scale) + zp, 0, 15); out = lut[q] * s_x
// depends on x only through mp = rint(log2(v)), v = x_int + bias (a small
// integer). So each block builds a 32-entry mp -> out table in shared memory
// (IEEE-exact __fdiv_rn / rintf so ties match XLA's fp32 semantics), and the
// streaming path is: FMUL + rint + cvt + clz + 64-bit square + LDS.
//
// mp is computed EXACTLY over the integer v:
//   n = floor(log2 v);  mp = n + (v*v >= 2^(2n+1))
// (ties impossible: 2^(n+0.5) irrational; verified decade-boundary margins
// exceed any fp32 log2 ulp error, rel_err == 0.0 on the bench).
// ---------------------------------------------------------------------------

__device__ __forceinline__ int lsq_mp(float x, float inv_sx, float bias) {
    float vf = rintf(x * inv_sx) + bias;       // x_int + bias (exact integers)
    unsigned v = (unsigned)vf;
    int n = 31 - __clz(v | 1u);                // |1 guards clz(0) only
    unsigned long long vv = (unsigned long long)v * (unsigned long long)v;
    return n + (int)(vv >> (2 * n + 1));       // 0 or 1
}

__global__ void __launch_bounds__(256)
lsq_main_kernel(const float4* __restrict__ in, float4* __restrict__ out,
                const float* __restrict__ s_x_p,
                const float* __restrict__ bias_p,
                const float* __restrict__ minv_p,
                const float* __restrict__ maxv_p,
                const float* __restrict__ lut,
                int n4) {
    __shared__ float s_tab[32];

    // Per-block table build: threads 0..31, one mp entry each. IEEE-exact ops
    // (independent of --use_fast_math), identical sequence to the reference:
    //   scale = (maxv-minv)/15; zp = rint(-minv/scale);
    //   q(mp) = clip(rint(-mp*c/scale) + zp, 0, 15); tab = lut[q]*s_x
    const float sx = __ldg(s_x_p);
    if (threadIdx.x < 32) {
        const float mn = __ldg(minv_p);
        const float mx = __ldg(maxv_p);
        const float c  = 40342.0f;                       // rint(2^15.3)
        const float scale = __fdiv_rn(mx - mn, 15.0f);
        const float zp    = rintf(__fdiv_rn(-mn, scale));
        float y  = (float)(-(int)threadIdx.x) * c;
        float qf = rintf(__fdiv_rn(y, scale)) + zp;
        qf = fminf(fmaxf(qf, 0.0f), 15.0f);
        s_tab[threadIdx.x] = __ldg(&lut[(int)qf]) * sx;
    }
    __syncthreads();

    int i = blockIdx.x * blockDim.x + threadIdx.x;
    if (i >= n4) return;

    const float inv_sx = __fdiv_rn(1.0f, sx);  // exact: s_x is a power of two
    const float bias   = __ldg(bias_p);

    float4 x = __ldg(&in[i]);
    float4 r;
    r.x = s_tab[lsq_mp(x.x, inv_sx, bias)];
    r.y = s_tab[lsq_mp(x.y, inv_sx, bias)];
    r.z = s_tab[lsq_mp(x.z, inv_sx, bias)];
    r.w = s_tab[lsq_mp(x.w, inv_sx, bias)];
    out[i] = r;
}

// Fill any trailing output elements (tuple second element: s_x scalar).
__global__ void lsq_tail_kernel(float* __restrict__ out,
                                const float* __restrict__ s_x,
                                int start, int total) {
    int i = start + blockIdx.x * blockDim.x + threadIdx.x;
    if (i < total) out[i] = __ldg(s_x);
}

extern "C" void kernel_launch(void* const* d_in, const int* in_sizes, int n_in,
                              void* d_out, int out_size) {
    const float* x_hat = (const float*)d_in[0];
    const float* s_x   = (const float*)d_in[1];
    const float* bias  = (const float*)d_in[2];
    const float* minv  = (const float*)d_in[3];
    const float* maxv  = (const float*)d_in[4];
    const float* lut   = (const float*)d_in[5];
    float* out = (float*)d_out;

    const int n = in_sizes[0];
    const int n4 = n >> 2;                       // N divisible by 4
    const int threads = 256;
    const int blocks = (n4 + threads - 1) / threads;

    lsq_main_kernel<<<blocks, threads>>>((const float4*)x_hat, (float4*)out,
                                         s_x, bias, minv, maxv, lut, n4);

    if (out_size > n) {
        int tail = out_size - n;
        int tthreads = 128;
        int tblocks = (tail + tthreads - 1) / tthreads;
        lsq_tail_kernel<<<tblocks, tthreads>>>(out, s_x, n, out_size);
    }
}

// round 5
// speedup vs baseline: 1.1767x; 1.1767x over previous
#include <cuda_runtime.h>
#include <stdint.h>

// ---------------------------------------------------------------------------
// LogSqrt2Quantizer — single persistent fused kernel.
//
// Math collapse: the whole reference chain
//   x_int = rint(x / s_x); y = rint(-log2(x_int + bias)) * c;
//   q = clip(rint(y/scale) + zp, 0, 15); out = lut[q] * s_x
// depends on x only through mp = rint(log2(v)), v = x_int + bias (a small
// integer in [66, 65602]). Each persistent block builds the 32-entry
// mp -> out table ONCE in shared memory with IEEE-exact fp32 ops
// (__fdiv_rn / rintf, flag-independent, matching XLA semantics — verified
// rel_err == 0.0 in round 3), then streams.
//
// mp is computed EXACTLY over the integer v:
//   n = floor(log2 v);  mp = n + (v*v >= 2^(2n+1))
// (ties impossible: 2^(n+0.5) irrational; decade-boundary margins exceed any
// fp32 log2 ulp error).
//
// Persistent grid (8 CTAs/SM) so the table-build prologue is paid ~1.2K
// times instead of ~98K (round-4 lesson: per-block prologues on CTA refills
// cost ~14% wall time). Hot path has no divides and no global scalar loads.
// ---------------------------------------------------------------------------

__device__ __forceinline__ int lsq_mp(float x, float inv_sx, float bias) {
    float vf = rintf(x * inv_sx) + bias;       // x_int + bias (exact integers)
    unsigned v = (unsigned)vf;
    int n = 31 - __clz(v | 1u);                // |1 guards clz(0) only
    unsigned long long vv = (unsigned long long)v * (unsigned long long)v;
    return n + (int)(vv >> (2 * n + 1));       // 0 or 1
}

__global__ void __launch_bounds__(256, 8)
lsq_fused_kernel(const float4* __restrict__ in, float4* __restrict__ out,
                 const float* __restrict__ s_x_p,
                 const float* __restrict__ bias_p,
                 const float* __restrict__ minv_p,
                 const float* __restrict__ maxv_p,
                 const float* __restrict__ lut,
                 int n4, int n, int out_size) {
    __shared__ float s_tab[32];
    __shared__ float s_par[2];                 // [0]=inv_sx  [1]=bias

    const unsigned tid = threadIdx.x;

    // --- per-block prologue (once per persistent block, ~1.2K total) ------
    if (tid < 32) {
        const float sx = __ldg(s_x_p);
        const float mn = __ldg(minv_p);
        const float mx = __ldg(maxv_p);
        const float c  = 40342.0f;                       // rint(2^15.3)
        const float scale = __fdiv_rn(mx - mn, 15.0f);
        const float zp    = rintf(__fdiv_rn(-mn, scale));
        float y  = (float)(-(int)tid) * c;
        float qf = rintf(__fdiv_rn(y, scale)) + zp;
        qf = fminf(fmaxf(qf, 0.0f), 15.0f);
        s_tab[tid] = __ldg(&lut[(int)qf]) * sx;
        if (tid == 0) {
            s_par[0] = __fdiv_rn(1.0f, sx);    // exact: s_x is a power of two
            s_par[1] = __ldg(bias_p);
        }
    } else if (tid < 64 && blockIdx.x == 0) {
        // Tuple tail: out[n .. out_size) = s_x (usually a single element).
        const float sx = __ldg(s_x_p);
        float* out_f = (float*)out;
        for (int j = n + (int)(tid - 32); j < out_size; j += 32)
            out_f[j] = sx;
    }
    __syncthreads();

    const float inv_sx = s_par[0];
    const float bias   = s_par[1];

    // --- persistent grid-stride stream ------------------------------------
    const int stride = gridDim.x * blockDim.x;
    for (int i = blockIdx.x * blockDim.x + tid; i < n4; i += stride) {
        float4 x = __ldcs(&in[i]);             // evict-first: pure stream
        float4 r;
        r.x = s_tab[lsq_mp(x.x, inv_sx, bias)];
        r.y = s_tab[lsq_mp(x.y, inv_sx, bias)];
        r.z = s_tab[lsq_mp(x.z, inv_sx, bias)];
        r.w = s_tab[lsq_mp(x.w, inv_sx, bias)];
        __stcs(&out[i], r);
    }
}

extern "C" void kernel_launch(void* const* d_in, const int* in_sizes, int n_in,
                              void* d_out, int out_size) {
    const float* x_hat = (const float*)d_in[0];
    const float* s_x   = (const float*)d_in[1];
    const float* bias  = (const float*)d_in[2];
    const float* minv  = (const float*)d_in[3];
    const float* maxv  = (const float*)d_in[4];
    const float* lut   = (const float*)d_in[5];
    float* out = (float*)d_out;

    const int n  = in_sizes[0];
    const int n4 = n >> 2;                     // N divisible by 4

    // Persistent launch: 8 CTAs per SM on GB300's 152 SMs.
    const int threads = 256;
    int blocks = 152 * 8;
    const int max_blocks = (n4 + threads - 1) / threads;
    if (blocks > max_blocks) blocks = max_blocks;

    lsq_fused_kernel<<<blocks, threads>>>((const float4*)x_hat, (float4*)out,
                                          s_x, bias, minv, maxv, lut,
                                          n4, n, out_size);
}